// round 5
// baseline (speedup 1.0000x reference)
#include <cuda_runtime.h>

// out[b,s,f,o] = sum_{t,k,c} x[b, s+t-2, f*(k+1), c] * W[t,k,c,o],  f*(k+1) < F
// x [4,1024,512,4] f32, W [5,4,4,4] f32, out [4,1024,512,4] f32.
//
// R5: R4 (c-packed FFMA2, smem-transposed weights, U=4) + software-pipelined
//     harmonics: straight-line k stages with per-stage row buffers, next
//     harmonic's 8 gather rows prefetched before the current harmonic's math
//     so FFMA2 work (~320 cyc) covers L2 gather latency (~260 cyc).

#define B_  4
#define S_  1024
#define F_  512
#define U_  4
#define NT  5
#define NK  4
#define TPB 128

typedef unsigned long long u64;

__device__ __forceinline__ u64 fma2(u64 a, u64 b, u64 c) {
    u64 d;
    asm("fma.rn.f32x2 %0, %1, %2, %3;" : "=l"(d) : "l"(a), "l"(b), "l"(c));
    return d;
}

__global__ __launch_bounds__(TPB, 5) void harm_conv_kernel(
    const float* __restrict__ x,
    const float* __restrict__ W,
    float* __restrict__ out)
{
    // Ws2[(k*NT+t)*4 + o] : floats (c0,c1,c2,c3) -> .x=(c0,c1) .y=(c2,c3)
    __shared__ ulonglong2 Ws2[NK * NT * 4];
    int tid = threadIdx.x;
    {
        float* wsf = reinterpret_cast<float*>(Ws2);
        for (int i = tid; i < NT * NK * 4 * 4; i += TPB) {
            int o = i & 3, c = (i >> 2) & 3, k = (i >> 4) & 3, t = i >> 6;
            wsf[((k * NT + t) * 4 + o) * 4 + c] = W[i];
        }
    }
    __syncthreads();

    int gid = blockIdx.x * TPB + tid;
    int f  = gid & (F_ - 1);                 // fastest: coalesced k=0 gather + stores
    int sb = (gid >> 9) & (S_ / U_ - 1);
    int b  = gid >> 17;
    int s0 = sb * U_;

    const ulonglong2* __restrict__ xb =
        reinterpret_cast<const ulonglong2*>(x) + (size_t)b * S_ * F_;

    u64 acc[U_][4];
#pragma unroll
    for (int j = 0; j < U_; ++j)
#pragma unroll
        for (int o = 0; o < 4; ++o) acc[j][o] = 0ull;

    // row loader: rows sp = s0-2 .. s0+U+1 of column fk
    auto loadRows = [&](ulonglong2* r, int fk) {
        const ulonglong2* __restrict__ col = xb + fk;
#pragma unroll
        for (int i = 0; i < U_ + 4; ++i) {
            int sp = s0 + i - 2;
            r[i] = (sp >= 0 && sp < S_) ? col[(size_t)sp * F_]
                                        : make_ulonglong2(0ull, 0ull);
        }
    };

    // compute one harmonic k against row buffer r
    auto compute = [&](const ulonglong2* r, int k) {
#pragma unroll
        for (int t = 0; t < NT; ++t) {
            const ulonglong2* wp = &Ws2[(k * NT + t) * 4];
            ulonglong2 w0 = wp[0], w1 = wp[1], w2 = wp[2], w3 = wp[3];
#pragma unroll
            for (int j = 0; j < U_; ++j) {
                ulonglong2 rv = r[j + t];
                acc[j][0] = fma2(rv.x, w0.x, acc[j][0]);
                acc[j][1] = fma2(rv.x, w1.x, acc[j][1]);
                acc[j][2] = fma2(rv.x, w2.x, acc[j][2]);
                acc[j][3] = fma2(rv.x, w3.x, acc[j][3]);
                acc[j][0] = fma2(rv.y, w0.y, acc[j][0]);
                acc[j][1] = fma2(rv.y, w1.y, acc[j][1]);
                acc[j][2] = fma2(rv.y, w2.y, acc[j][2]);
                acc[j][3] = fma2(rv.y, w3.y, acc[j][3]);
            }
        }
    };

    // warp-coherent harmonic validity (monotone in k)
    bool v1 = (2 * f < F_);
    bool v2 = (3 * f < F_);
    bool v3 = (4 * f < F_);

    ulonglong2 r0[U_ + 4], r1[U_ + 4], r2[U_ + 4], r3[U_ + 4];

    loadRows(r0, f);                 // k=0 always valid
    if (v1) loadRows(r1, 2 * f);     // prefetch k=1
    compute(r0, 0);
    if (v1) {
        if (v2) loadRows(r2, 3 * f); // prefetch k=2
        compute(r1, 1);
        if (v2) {
            if (v3) loadRows(r3, 4 * f); // prefetch k=3
            compute(r2, 2);
            if (v3) compute(r3, 3);
        }
    }

    // epilogue: fold the two c-halves per output
    float4* __restrict__ o4 =
        reinterpret_cast<float4*>(out) + ((size_t)(b * S_ + s0)) * F_ + f;
#pragma unroll
    for (int j = 0; j < U_; ++j) {
        float2 a0 = reinterpret_cast<float2&>(acc[j][0]);
        float2 a1 = reinterpret_cast<float2&>(acc[j][1]);
        float2 a2 = reinterpret_cast<float2&>(acc[j][2]);
        float2 a3 = reinterpret_cast<float2&>(acc[j][3]);
        o4[(size_t)j * F_] = make_float4(a0.x + a0.y, a1.x + a1.y,
                                         a2.x + a2.y, a3.x + a3.y);
    }
}

extern "C" void kernel_launch(void* const* d_in, const int* in_sizes, int n_in,
                              void* d_out, int out_size)
{
    const float* x = (const float*)d_in[0];
    const float* W = (const float*)d_in[1];
    float* out = (float*)d_out;

    int total = B_ * (S_ / U_) * F_;         // one thread per (b, s-block, f)
    harm_conv_kernel<<<total / TPB, TPB>>>(x, W, out);
}

// round 6
// speedup vs baseline: 1.4415x; 1.4415x over previous
#include <cuda_runtime.h>

// out[b,s,f,o] = sum_{t,k,c} x[b, s+t-2, f*(k+1), c] * W[t,k,c,o],  f*(k+1) < F
// x [4,1024,512,4] f32, W [5,4,4,4] f32, out [4,1024,512,4] f32.
//
// R6: c-packed FFMA2 (R4) + rolling 4-row ring buffer (t-outer, 16 regs) +
//     weights in __constant__ (transposed on device, LDCU/UR path: zero GPR,
//     zero L1TEX) + 64-reg cap for ~50% occupancy.

#define B_  4
#define S_  1024
#define F_  512
#define U_  4
#define NT  5
#define NK  4
#define TPB 256

typedef unsigned long long u64;

// Wc2[(k*NT+t)*4 + o] : floats (c0,c1,c2,c3) -> .x=(c0,c1) .y=(c2,c3)
__constant__ ulonglong2 Wc2[NK * NT * 4];
__device__ float Wt_scratch[NT * NK * 16];     // transposed weights staging

__global__ void transpose_w_kernel(const float* __restrict__ W)
{
    int i = threadIdx.x;                        // 320 threads, one element each
    if (i < NT * NK * 16) {
        // src linear: ((t*NK + k)*4 + c)*4 + o
        int o = i & 3, c = (i >> 2) & 3, k = (i >> 4) & 3, t = i >> 6;
        Wt_scratch[((k * NT + t) * 4 + o) * 4 + c] = W[i];
    }
}

__device__ __forceinline__ u64 fma2(u64 a, u64 b, u64 c) {
    u64 d;
    asm("fma.rn.f32x2 %0, %1, %2, %3;" : "=l"(d) : "l"(a), "l"(b), "l"(c));
    return d;
}

__global__ __launch_bounds__(TPB, 4) void harm_conv_kernel(
    const float* __restrict__ x,
    float* __restrict__ out)
{
    int gid = blockIdx.x * TPB + threadIdx.x;
    int f  = gid & (F_ - 1);                   // fastest: coalesced k=0 gather + stores
    int sb = (gid >> 9) & (S_ / U_ - 1);
    int b  = gid >> 17;
    int s0 = sb * U_;

    const ulonglong2* __restrict__ xb =
        reinterpret_cast<const ulonglong2*>(x) + (size_t)b * S_ * F_;

    u64 acc[U_][4];                            // [j][o], packed over c-pairs
#pragma unroll
    for (int j = 0; j < U_; ++j)
#pragma unroll
        for (int o = 0; o < 4; ++o) acc[j][o] = 0ull;

    for (int k = 0; k < NK; ++k) {
        int fk = f * (k + 1);
        if (fk >= F_) break;                   // monotone in k, warp-coherent
        const ulonglong2* __restrict__ col = xb + fk;

        // ring buffer: w[m & 3] holds row m (sp = s0 + m - 2), m = 0..7
        ulonglong2 w[4];
#pragma unroll
        for (int m = 0; m < 4; ++m) {
            int sp = s0 + m - 2;
            w[m] = (sp >= 0 && sp < S_) ? col[(size_t)sp * F_]
                                        : make_ulonglong2(0ull, 0ull);
        }

#pragma unroll
        for (int t = 0; t < NT; ++t) {
            ulonglong2 w0 = Wc2[(k * NT + t) * 4 + 0];
            ulonglong2 w1 = Wc2[(k * NT + t) * 4 + 1];
            ulonglong2 w2 = Wc2[(k * NT + t) * 4 + 2];
            ulonglong2 w3 = Wc2[(k * NT + t) * 4 + 3];
#pragma unroll
            for (int j = 0; j < U_; ++j) {
                ulonglong2 rv = w[(t + j) & 3];
                acc[j][0] = fma2(rv.x, w0.x, acc[j][0]);
                acc[j][1] = fma2(rv.x, w1.x, acc[j][1]);
                acc[j][2] = fma2(rv.x, w2.x, acc[j][2]);
                acc[j][3] = fma2(rv.x, w3.x, acc[j][3]);
                acc[j][0] = fma2(rv.y, w0.y, acc[j][0]);
                acc[j][1] = fma2(rv.y, w1.y, acc[j][1]);
                acc[j][2] = fma2(rv.y, w2.y, acc[j][2]);
                acc[j][3] = fma2(rv.y, w3.y, acc[j][3]);
            }
            if (t < NT - 1) {                  // load row m = t+4 into w[t & 3]
                int sp = s0 + t + 2;
                w[t & 3] = (sp < S_) ? col[(size_t)sp * F_]
                                     : make_ulonglong2(0ull, 0ull);
            }
        }
    }

    // epilogue: fold the two c-halves per output
    float4* __restrict__ o4 =
        reinterpret_cast<float4*>(out) + ((size_t)(b * S_ + s0)) * F_ + f;
#pragma unroll
    for (int j = 0; j < U_; ++j) {
        float2 a0 = reinterpret_cast<float2&>(acc[j][0]);
        float2 a1 = reinterpret_cast<float2&>(acc[j][1]);
        float2 a2 = reinterpret_cast<float2&>(acc[j][2]);
        float2 a3 = reinterpret_cast<float2&>(acc[j][3]);
        o4[(size_t)j * F_] = make_float4(a0.x + a0.y, a1.x + a1.y,
                                         a2.x + a2.y, a3.x + a3.y);
    }
}

extern "C" void kernel_launch(void* const* d_in, const int* in_sizes, int n_in,
                              void* d_out, int out_size)
{
    const float* x = (const float*)d_in[0];
    const float* W = (const float*)d_in[1];
    float* out = (float*)d_out;

    // 1) transpose weights into staging buffer (device-side)
    transpose_w_kernel<<<1, NT * NK * 16>>>(W);

    // 2) stage into the constant bank (capture-legal async D2D)
    void* wt_dev = nullptr;
    cudaGetSymbolAddress(&wt_dev, Wt_scratch);
    cudaMemcpyToSymbolAsync(Wc2, wt_dev, NT * NK * 16 * sizeof(float), 0,
                            cudaMemcpyDeviceToDevice, 0);

    // 3) main kernel
    int total = B_ * (S_ / U_) * F_;           // one thread per (b, s-block, f)
    harm_conv_kernel<<<total / TPB, TPB>>>(x, out);
}